// round 4
// baseline (speedup 1.0000x reference)
#include <cuda_runtime.h>
#include <cuda_bf16.h>

// BackwardRPM: 16384 independent 200-step projected-gradient solves.
//   step: h = tanh(W1^T u + b1); z = A h + d; grad6 = R6^T z; u = clamp(u - LR*grad6)
//   with A = R @ W2^T (8x64), d_p = R[p] . (b2 - spec)  (precomputed)
//
// One thread per batch element. Weights live in shared memory as packed
// float2 pairs; all per-step math uses fma.rn.f32x2 (sm_100+ packed FMA).

#define STEPS 200
#define LRATE 0.01f
#define BATCH 16384
#define HID   64
#define HID2  32      // packed pairs
#define PROJ  8
#define NSPEC 40
#define NU    6

typedef unsigned long long u64;

// packed f32x2 helpers
#define PK(d, lo, hi)  asm("mov.b64 %0, {%1, %2};" : "=l"(d) : "f"(lo), "f"(hi))
#define UPK(lo, hi, s) asm("mov.b64 {%0, %1}, %2;" : "=f"(lo), "=f"(hi) : "l"(s))
#define FMA2(d, a, b, c) \
    asm("fma.rn.f32x2 %0, %1, %2, %3;" : "=l"(d) : "l"(a), "l"(b), "l"(c))
#define MUL2(d, a, b) \
    asm("mul.rn.f32x2 %0, %1, %2;" : "=l"(d) : "l"(a), "l"(b))

// tanh(x) = 1 - 2/(exp(2x)+1); exp(2x) = 2^(x * 2*log2(e))
// ex2/rcp saturate correctly: x->+inf => 1, x->-inf => -1. err ~1e-6.
__device__ __forceinline__ float tanh_fast(float x) {
    float t, r;
    asm("ex2.approx.ftz.f32 %0, %1;" : "=f"(t) : "f"(x * 2.8853900817779268f));
    asm("rcp.approx.ftz.f32 %0, %1;" : "=f"(r) : "f"(t + 1.0f));
    return fmaf(-2.0f, r, 1.0f);
}

__global__ void __launch_bounds__(128)
backward_rpm_kernel(const float* __restrict__ spectrum,  // (16384, 40)
                    const float* __restrict__ W1,        // (6, 64)
                    const float* __restrict__ b1,        // (64,)
                    const float* __restrict__ W2,        // (64, 40)
                    const float* __restrict__ b2,        // (40,)
                    const float* __restrict__ R,         // (8, 40)
                    float* __restrict__ out)             // (16384, 6)
{
    // ---- shared weights, packed as 64-bit float pairs ----
    __shared__ u64  sW1[NU * HID2];     // W1[k][2j],W1[k][2j+1]
    __shared__ u64  sB1[HID2];
    __shared__ u64  sA [PROJ * HID2];   // A[p][2j],A[p][2j+1]
    __shared__ u64  sR [PROJ * (NSPEC / 2)];  // full R rows as pairs
    __shared__ float sB2[NSPEC];

    const int tid = threadIdx.x;

    // flat copies (pair layout == contiguous source layout)
    {
        float* fW1 = (float*)sW1;
        float* fB1 = (float*)sB1;
        float* fR  = (float*)sR;
        for (int i = tid; i < NU * HID; i += 128) fW1[i] = W1[i];
        for (int i = tid; i < HID;      i += 128) fB1[i] = b1[i];
        for (int i = tid; i < PROJ * NSPEC; i += 128) fR[i] = R[i];
        for (int i = tid; i < NSPEC;    i += 128) sB2[i] = b2[i];

        // A[p][j] = sum_k R[p][k] * W2[j][k]   (512 entries, 4 per thread)
        float* fA = (float*)sA;
        for (int idx = tid; idx < PROJ * HID; idx += 128) {
            int p = idx >> 6;
            int j = idx & 63;
            float acc = 0.0f;
            #pragma unroll
            for (int k = 0; k < NSPEC; k++)
                acc = fmaf(R[p * NSPEC + k], W2[j * NSPEC + k], acc);
            fA[idx] = acc;
        }
    }
    __syncthreads();

    const int elem = blockIdx.x * 128 + tid;
    const float* sp = spectrum + elem * NSPEC;
    const float* fR = (const float*)sR;

    // d_p = R[p] . (b2 - spec), stored packed as (d_p, 0)
    u64 d2[PROJ];
    #pragma unroll
    for (int p = 0; p < PROJ; p++) {
        float acc = 0.0f;
        #pragma unroll
        for (int k = 0; k < NSPEC; k++)
            acc = fmaf(fR[p * NSPEC + k], sB2[k] - sp[k], acc);
        PK(d2[p], acc, 0.0f);
    }

    // u scalars + duplicated-packed form
    float u[NU];
    u64   ud[NU];
    #pragma unroll
    for (int k = 0; k < NU; k++) { u[k] = 0.5f; PK(ud[k], u[k], u[k]); }

    #pragma unroll 1
    for (int step = 0; step < STEPS; step++) {
        // ---- pre-activation: pre[j2] = b1 + sum_k u_k * W1[k][j2] ----
        u64 pre[HID2];
        #pragma unroll
        for (int j = 0; j < HID2; j++) pre[j] = sB1[j];
        #pragma unroll
        for (int k = 0; k < NU; k++) {
            #pragma unroll
            for (int j = 0; j < HID2; j++)
                FMA2(pre[j], ud[k], sW1[k * HID2 + j], pre[j]);
        }

        // ---- h = tanh(pre), kept packed in-place ----
        #pragma unroll
        for (int j = 0; j < HID2; j++) {
            float a, b;
            UPK(a, b, pre[j]);
            a = tanh_fast(a);
            b = tanh_fast(b);
            PK(pre[j], a, b);
        }

        // ---- z = A h + d (packed partial sums) ----
        u64 z2[PROJ];
        #pragma unroll
        for (int p = 0; p < PROJ; p++) z2[p] = d2[p];
        #pragma unroll
        for (int j = 0; j < HID2; j++) {
            #pragma unroll
            for (int p = 0; p < PROJ; p++)
                FMA2(z2[p], sA[p * HID2 + j], pre[j], z2[p]);
        }

        // ---- finalize z_p (horizontal add), duplicate-pack ----
        u64 zd[PROJ];
        #pragma unroll
        for (int p = 0; p < PROJ; p++) {
            float a, b;
            UPK(a, b, z2[p]);
            float zp = a + b;
            PK(zd[p], zp, zp);
        }

        // ---- grad pairs: g2[jj] = sum_p (R[p][2jj],R[p][2jj+1]) * z_p ----
        u64 g2[3];
        #pragma unroll
        for (int jj = 0; jj < 3; jj++)
            MUL2(g2[jj], sR[0 * (NSPEC / 2) + jj], zd[0]);
        #pragma unroll
        for (int p = 1; p < PROJ; p++) {
            #pragma unroll
            for (int jj = 0; jj < 3; jj++)
                FMA2(g2[jj], sR[p * (NSPEC / 2) + jj], zd[p], g2[jj]);
        }

        // ---- update + clamp ----
        #pragma unroll
        for (int jj = 0; jj < 3; jj++) {
            float ga, gb;
            UPK(ga, gb, g2[jj]);
            float ua = fmaf(-LRATE, ga, u[2 * jj]);
            float ub = fmaf(-LRATE, gb, u[2 * jj + 1]);
            ua = fminf(fmaxf(ua, 0.0f), 1.0f);
            ub = fminf(fmaxf(ub, 0.0f), 1.0f);
            u[2 * jj]     = ua;
            u[2 * jj + 1] = ub;
            PK(ud[2 * jj],     ua, ua);
            PK(ud[2 * jj + 1], ub, ub);
        }
    }

    #pragma unroll
    for (int k = 0; k < NU; k++)
        out[elem * NU + k] = u[k];
}

extern "C" void kernel_launch(void* const* d_in, const int* in_sizes, int n_in,
                              void* d_out, int out_size) {
    const float* spectrum = (const float*)d_in[0];
    const float* W1 = (const float*)d_in[1];
    const float* b1 = (const float*)d_in[2];
    const float* W2 = (const float*)d_in[3];
    const float* b2 = (const float*)d_in[4];
    const float* R  = (const float*)d_in[5];
    float* out = (float*)d_out;

    backward_rpm_kernel<<<BATCH / 128, 128>>>(spectrum, W1, b1, W2, b2, R, out);
}

// round 7
// speedup vs baseline: 10.3788x; 10.3788x over previous
#include <cuda_runtime.h>
#include <cuda_bf16.h>

// BackwardRPM: 16384 independent 200-step projected-gradient solves.
//   step: h = tanh(W1^T u + b1); z = A h + d; grad6 = R6^T z; u = clamp(u - LR*grad6)
//   with A = R @ W2^T (8x64), d_p = R[p] . (b2 - spec)  (precomputed)
//
// One thread per batch element. Weights live in shared memory as packed
// float2 pairs; all per-step math uses fma.rn.f32x2 (sm_100+ packed FMA).
//
// R4 fix: __launch_bounds__(128, 1) — the R3 build capped at 32 regs and
// spilled all accumulators to local memory (regs=32, issue=2.4%).

#define STEPS 200
#define LRATE 0.01f
#define BATCH 16384
#define HID   64
#define HID2  32      // packed pairs
#define PROJ  8
#define NSPEC 40
#define NU    6

typedef unsigned long long u64;

// packed f32x2 helpers
#define PK(d, lo, hi)  asm("mov.b64 %0, {%1, %2};" : "=l"(d) : "f"(lo), "f"(hi))
#define UPK(lo, hi, s) asm("mov.b64 {%0, %1}, %2;" : "=f"(lo), "=f"(hi) : "l"(s))
#define FMA2(d, a, b, c) \
    asm("fma.rn.f32x2 %0, %1, %2, %3;" : "=l"(d) : "l"(a), "l"(b), "l"(c))
#define MUL2(d, a, b) \
    asm("mul.rn.f32x2 %0, %1, %2;" : "=l"(d) : "l"(a), "l"(b))

// tanh(x) = 1 - 2/(exp(2x)+1); exp(2x) = 2^(x * 2*log2(e))
// ex2/rcp saturate correctly: x->+inf => 1, x->-inf => -1. err ~1e-6.
__device__ __forceinline__ float tanh_fast(float x) {
    float t, r;
    asm("ex2.approx.ftz.f32 %0, %1;" : "=f"(t) : "f"(x * 2.8853900817779268f));
    asm("rcp.approx.ftz.f32 %0, %1;" : "=f"(r) : "f"(t + 1.0f));
    return fmaf(-2.0f, r, 1.0f);
}

__global__ void __launch_bounds__(128, 1)
backward_rpm_kernel(const float* __restrict__ spectrum,  // (16384, 40)
                    const float* __restrict__ W1,        // (6, 64)
                    const float* __restrict__ b1,        // (64,)
                    const float* __restrict__ W2,        // (64, 40)
                    const float* __restrict__ b2,        // (40,)
                    const float* __restrict__ R,         // (8, 40)
                    float* __restrict__ out)             // (16384, 6)
{
    // ---- shared weights, packed as 64-bit float pairs ----
    __shared__ u64  sW1[NU * HID2];     // W1[k][2j],W1[k][2j+1]
    __shared__ u64  sB1[HID2];
    __shared__ u64  sA [PROJ * HID2];   // A[p][2j],A[p][2j+1]
    __shared__ u64  sR [PROJ * (NSPEC / 2)];  // full R rows as pairs
    __shared__ float sB2[NSPEC];

    const int tid = threadIdx.x;

    // flat copies (pair layout == contiguous source layout)
    {
        float* fW1 = (float*)sW1;
        float* fB1 = (float*)sB1;
        float* fR  = (float*)sR;
        for (int i = tid; i < NU * HID; i += 128) fW1[i] = W1[i];
        for (int i = tid; i < HID;      i += 128) fB1[i] = b1[i];
        for (int i = tid; i < PROJ * NSPEC; i += 128) fR[i] = R[i];
        for (int i = tid; i < NSPEC;    i += 128) sB2[i] = b2[i];

        // A[p][j] = sum_k R[p][k] * W2[j][k]   (512 entries, 4 per thread)
        float* fA = (float*)sA;
        for (int idx = tid; idx < PROJ * HID; idx += 128) {
            int p = idx >> 6;
            int j = idx & 63;
            float acc = 0.0f;
            #pragma unroll
            for (int k = 0; k < NSPEC; k++)
                acc = fmaf(R[p * NSPEC + k], W2[j * NSPEC + k], acc);
            fA[idx] = acc;
        }
    }
    __syncthreads();

    const int elem = blockIdx.x * 128 + tid;
    const float* sp = spectrum + elem * NSPEC;
    const float* fR = (const float*)sR;

    // d_p = R[p] . (b2 - spec), stored packed as (d_p, 0)
    u64 d2[PROJ];
    #pragma unroll
    for (int p = 0; p < PROJ; p++) {
        float acc = 0.0f;
        #pragma unroll
        for (int k = 0; k < NSPEC; k++)
            acc = fmaf(fR[p * NSPEC + k], sB2[k] - sp[k], acc);
        PK(d2[p], acc, 0.0f);
    }

    // u scalars + duplicated-packed form
    float u[NU];
    u64   ud[NU];
    #pragma unroll
    for (int k = 0; k < NU; k++) { u[k] = 0.5f; PK(ud[k], u[k], u[k]); }

    #pragma unroll 1
    for (int step = 0; step < STEPS; step++) {
        // ---- pre-activation: pre[j2] = b1 + sum_k u_k * W1[k][j2] ----
        u64 pre[HID2];
        #pragma unroll
        for (int j = 0; j < HID2; j++) pre[j] = sB1[j];
        #pragma unroll
        for (int k = 0; k < NU; k++) {
            #pragma unroll
            for (int j = 0; j < HID2; j++)
                FMA2(pre[j], ud[k], sW1[k * HID2 + j], pre[j]);
        }

        // ---- h = tanh(pre), kept packed in-place ----
        #pragma unroll
        for (int j = 0; j < HID2; j++) {
            float a, b;
            UPK(a, b, pre[j]);
            a = tanh_fast(a);
            b = tanh_fast(b);
            PK(pre[j], a, b);
        }

        // ---- z = A h + d (packed partial sums) ----
        u64 z2[PROJ];
        #pragma unroll
        for (int p = 0; p < PROJ; p++) z2[p] = d2[p];
        #pragma unroll
        for (int j = 0; j < HID2; j++) {
            #pragma unroll
            for (int p = 0; p < PROJ; p++)
                FMA2(z2[p], sA[p * HID2 + j], pre[j], z2[p]);
        }

        // ---- finalize z_p (horizontal add), duplicate-pack ----
        u64 zd[PROJ];
        #pragma unroll
        for (int p = 0; p < PROJ; p++) {
            float a, b;
            UPK(a, b, z2[p]);
            float zp = a + b;
            PK(zd[p], zp, zp);
        }

        // ---- grad pairs: g2[jj] = sum_p (R[p][2jj],R[p][2jj+1]) * z_p ----
        u64 g2[3];
        #pragma unroll
        for (int jj = 0; jj < 3; jj++)
            MUL2(g2[jj], sR[0 * (NSPEC / 2) + jj], zd[0]);
        #pragma unroll
        for (int p = 1; p < PROJ; p++) {
            #pragma unroll
            for (int jj = 0; jj < 3; jj++)
                FMA2(g2[jj], sR[p * (NSPEC / 2) + jj], zd[p], g2[jj]);
        }

        // ---- update + clamp ----
        #pragma unroll
        for (int jj = 0; jj < 3; jj++) {
            float ga, gb;
            UPK(ga, gb, g2[jj]);
            float ua = fmaf(-LRATE, ga, u[2 * jj]);
            float ub = fmaf(-LRATE, gb, u[2 * jj + 1]);
            ua = fminf(fmaxf(ua, 0.0f), 1.0f);
            ub = fminf(fmaxf(ub, 0.0f), 1.0f);
            u[2 * jj]     = ua;
            u[2 * jj + 1] = ub;
            PK(ud[2 * jj],     ua, ua);
            PK(ud[2 * jj + 1], ub, ub);
        }
    }

    #pragma unroll
    for (int k = 0; k < NU; k++)
        out[elem * NU + k] = u[k];
}

extern "C" void kernel_launch(void* const* d_in, const int* in_sizes, int n_in,
                              void* d_out, int out_size) {
    const float* spectrum = (const float*)d_in[0];
    const float* W1 = (const float*)d_in[1];
    const float* b1 = (const float*)d_in[2];
    const float* W2 = (const float*)d_in[3];
    const float* b2 = (const float*)d_in[4];
    const float* R  = (const float*)d_in[5];
    float* out = (float*)d_out;

    backward_rpm_kernel<<<BATCH / 128, 128>>>(spectrum, W1, b1, W2, b2, R, out);
}

// round 9
// speedup vs baseline: 26.5998x; 2.5629x over previous
#include <cuda_runtime.h>
#include <cuda_bf16.h>

// BackwardRPM: 16384 independent 200-step projected-gradient solves.
// R7 reformulation: grad6 = M h + c with M = R6^T R W2^T (6x64),
//                   c = R6^T R (b2 - spec) (6 per element, precomputed).
// 4 threads per element (hidden dim split 4 ways, pairs striped mod 4),
// grad partials combined with shfl.bfly over the 4-lane group.
// 512 threads/block, grid=128 -> 4 warps/SMSP for latency hiding.

#define STEPS 200
#define LRATE 0.01f
#define BATCH 16384
#define HID   64
#define HID2  32
#define PROJ  8
#define NSPEC 40
#define NU    6

typedef unsigned long long u64;

#define PK(d, lo, hi)  asm("mov.b64 %0, {%1, %2};" : "=l"(d) : "f"(lo), "f"(hi))
#define UPK(lo, hi, s) asm("mov.b64 {%0, %1}, %2;" : "=f"(lo), "=f"(hi) : "l"(s))
#define FMA2(d, a, b, c) \
    asm("fma.rn.f32x2 %0, %1, %2, %3;" : "=l"(d) : "l"(a), "l"(b), "l"(c))
#define MUL2(d, a, b) \
    asm("mul.rn.f32x2 %0, %1, %2;" : "=l"(d) : "l"(a), "l"(b))

// tanh(x) = 1 - 2/(exp(2x)+1); exp(2x) = 2^(x * 2*log2(e))
// ex2/rcp saturate correctly at +/-inf. err ~1e-6.
__device__ __forceinline__ float ex2f(float x) {
    float t;
    asm("ex2.approx.ftz.f32 %0, %1;" : "=f"(t) : "f"(x));
    return t;
}
__device__ __forceinline__ float rcpf(float x) {
    float t;
    asm("rcp.approx.ftz.f32 %0, %1;" : "=f"(t) : "f"(x));
    return t;
}

__global__ void __launch_bounds__(512, 1)
backward_rpm_kernel(const float* __restrict__ spectrum,  // (16384, 40)
                    const float* __restrict__ W1,        // (6, 64)
                    const float* __restrict__ b1,        // (64,)
                    const float* __restrict__ W2,        // (64, 40)
                    const float* __restrict__ b2,        // (40,)
                    const float* __restrict__ R,         // (8, 40)
                    float* __restrict__ out)             // (16384, 6)
{
    __shared__ float sA [PROJ * HID];       // scratch: A = R W2^T
    __shared__ u64   sW1p[NU * HID2];       // W1 packed pairs
    __shared__ u64   sB1p[HID2];
    __shared__ u64   sMp [NU * HID2];       // M = R6^T A, packed pairs
    __shared__ float sP  [NU * NSPEC];      // P = R6^T R
    __shared__ float sB2 [NSPEC];

    const int tid = threadIdx.x;

    // ---- one-time weight prep ----
    {
        float* fW1 = (float*)sW1p;
        for (int i = tid; i < NU * HID; i += 512) fW1[i] = W1[i];
        if (tid < HID)   ((float*)sB1p)[tid] = b1[tid];
        if (tid < NSPEC) sB2[tid] = b2[tid];

        // A[p][j] = sum_k R[p][k] * W2[j][k]  (512 entries, one per thread)
        {
            int p = tid >> 6, j = tid & 63;
            float acc = 0.0f;
            #pragma unroll
            for (int k = 0; k < NSPEC; k++)
                acc = fmaf(R[p * NSPEC + k], W2[j * NSPEC + k], acc);
            sA[tid] = acc;
        }
        __syncthreads();

        // M[i][j] = sum_p R[p][i] * A[p][j]  (384 entries)
        float* fM = (float*)sMp;
        for (int idx = tid; idx < NU * HID; idx += 512) {
            int i = idx >> 6, j = idx & 63;
            float acc = 0.0f;
            #pragma unroll
            for (int p = 0; p < PROJ; p++)
                acc = fmaf(R[p * NSPEC + i], sA[p * HID + j], acc);
            fM[idx] = acc;
        }
        // P[i][k] = sum_p R[p][i] * R[p][k]  (240 entries)
        for (int idx = tid; idx < NU * NSPEC; idx += 512) {
            int i = idx / NSPEC, k = idx % NSPEC;
            float acc = 0.0f;
            #pragma unroll
            for (int p = 0; p < PROJ; p++)
                acc = fmaf(R[p * NSPEC + i], R[p * NSPEC + k], acc);
            sP[idx] = acc;
        }
        __syncthreads();
    }

    // ---- per-element constants ----
    const int s    = tid & 3;                        // hidden-dim slice
    const int elem = blockIdx.x * 128 + (tid >> 2);
    const float* sp = spectrum + elem * NSPEC;

    // cl[i] = LR * (P (b2 - spec))[i]   (duplicated across the 4 slices)
    float cl[NU];
    #pragma unroll
    for (int i = 0; i < NU; i++) {
        float acc = 0.0f;
        #pragma unroll
        for (int k = 0; k < NSPEC; k++)
            acc = fmaf(sP[i * NSPEC + k], sB2[k] - sp[k], acc);
        cl[i] = LRATE * acc;
    }

    // packed constants
    u64 K2, NEG2, ONE2;
    PK(K2,   2.8853900817779268f, 2.8853900817779268f);  // 2*log2(e)
    PK(NEG2, -2.0f, -2.0f);
    PK(ONE2,  1.0f,  1.0f);

    float u[NU];
    u64   ud[NU];
    #pragma unroll
    for (int k = 0; k < NU; k++) { u[k] = 0.5f; PK(ud[k], u[k], u[k]); }

    #pragma unroll 1
    for (int step = 0; step < STEPS; step++) {
        // ---- pre-activation for this slice's 8 pairs (jp = jj*4 + s) ----
        u64 pre[8];
        #pragma unroll
        for (int jj = 0; jj < 8; jj++) pre[jj] = sB1p[jj * 4 + s];
        #pragma unroll
        for (int k = 0; k < NU; k++) {
            #pragma unroll
            for (int jj = 0; jj < 8; jj++)
                FMA2(pre[jj], ud[k], sW1p[k * HID2 + jj * 4 + s], pre[jj]);
        }

        // ---- h = tanh(pre) ----
        #pragma unroll
        for (int jj = 0; jj < 8; jj++) {
            u64 t;
            MUL2(t, pre[jj], K2);
            float a, b;
            UPK(a, b, t);
            float ra = rcpf(ex2f(a) + 1.0f);
            float rb = rcpf(ex2f(b) + 1.0f);
            PK(t, ra, rb);
            FMA2(pre[jj], NEG2, t, ONE2);   // 1 - 2*r
        }

        // ---- grad partials: gp[i] = sum_{this slice's jp} M2[i][jp] * h2[jp] ----
        u64 gp[NU];
        #pragma unroll
        for (int i = 0; i < NU; i++)
            MUL2(gp[i], sMp[i * HID2 + s], pre[0]);
        #pragma unroll
        for (int jj = 1; jj < 8; jj++) {
            #pragma unroll
            for (int i = 0; i < NU; i++)
                FMA2(gp[i], sMp[i * HID2 + jj * 4 + s], pre[jj], gp[i]);
        }

        // ---- horizontal + 4-lane reduce ----
        float g[NU];
        #pragma unroll
        for (int i = 0; i < NU; i++) {
            float a, b;
            UPK(a, b, gp[i]);
            g[i] = a + b;
        }
        #pragma unroll
        for (int i = 0; i < NU; i++)
            g[i] += __shfl_xor_sync(0xFFFFFFFFu, g[i], 1);
        #pragma unroll
        for (int i = 0; i < NU; i++)
            g[i] += __shfl_xor_sync(0xFFFFFFFFu, g[i], 2);

        // ---- update + clamp (all 4 lanes identical) ----
        #pragma unroll
        for (int i = 0; i < NU; i++) {
            float t = fmaf(-LRATE, g[i], u[i]) - cl[i];
            t = fminf(fmaxf(t, 0.0f), 1.0f);
            u[i] = t;
            PK(ud[i], t, t);
        }
    }

    if (s == 0) {
        #pragma unroll
        for (int k = 0; k < NU; k++)
            out[elem * NU + k] = u[k];
    }
}

extern "C" void kernel_launch(void* const* d_in, const int* in_sizes, int n_in,
                              void* d_out, int out_size) {
    const float* spectrum = (const float*)d_in[0];
    const float* W1 = (const float*)d_in[1];
    const float* b1 = (const float*)d_in[2];
    const float* W2 = (const float*)d_in[3];
    const float* b2 = (const float*)d_in[4];
    const float* R  = (const float*)d_in[5];
    float* out = (float*)d_out;

    backward_rpm_kernel<<<BATCH / 128, 512>>>(spectrum, W1, b1, W2, b2, R, out);
}